// round 13
// baseline (speedup 1.0000x reference)
#include <cuda_runtime.h>
#include <math.h>

// S=4, B=4, T=4096, D=1024 (fixed per reference setup_inputs)
#define S_STREAMS 4
#define T_LEN 4096
#define D_DIM 1024
#define DV (D_DIM / 4)          // 256 float4 per row
#define SINKHORN_ITERS 20
#define EPS 1e-5f

// precomputed scalars: [0..3]=h_pre, [4..7]=c
__device__ float g_hc_params[8];

// Primary kernel (PDL): trigger the dependent launch IMMEDIATELY, then do the
// ~1.3k-cycle serial fast-math precompute.
__global__ void hc_precompute_kernel(const float* __restrict__ H_pre_logits,
                                     const float* __restrict__ H_post_logits,
                                     const float* __restrict__ H_res) {
    cudaTriggerProgrammaticLaunchCompletion();

    float M[4][4];
    #pragma unroll
    for (int i = 0; i < 4; i++)
        #pragma unroll
        for (int j = 0; j < 4; j++)
            M[i][j] = __expf(H_res[i * 4 + j]);

    #pragma unroll 4
    for (int it = 0; it < SINKHORN_ITERS; it++) {
        #pragma unroll
        for (int i = 0; i < 4; i++) {
            float s = (M[i][0] + M[i][1]) + (M[i][2] + M[i][3]) + EPS;
            float inv = __fdividef(1.0f, s);
            #pragma unroll
            for (int j = 0; j < 4; j++) M[i][j] *= inv;
        }
        #pragma unroll
        for (int j = 0; j < 4; j++) {
            float s = (M[0][j] + M[1][j]) + (M[2][j] + M[3][j]) + EPS;
            float inv = __fdividef(1.0f, s);
            #pragma unroll
            for (int i = 0; i < 4; i++) M[i][j] *= inv;
        }
    }

    float h_post[4];
    #pragma unroll
    for (int r = 0; r < 4; r++)
        h_post[r] = 2.0f * __fdividef(1.0f, 1.0f + __expf(-H_post_logits[r]));

    #pragma unroll
    for (int s = 0; s < 4; s++) {
        g_hc_params[s] = __fdividef(1.0f, 1.0f + __expf(-H_pre_logits[s]));
        float c = 0.0f;
        #pragma unroll
        for (int r = 0; r < 4; r++) c += M[s][r] * h_post[r];
        g_hc_params[4 + s] = c;
    }
}

// Secondary kernel (PDL): 128 threads, TWO adjacent tokens per block.
// Each thread front-batches 16 independent LDG.128 (2 chunks x 4 streams x
// 2 tokens = 8KB/warp in flight). Both tokens' RMS reductions share ONE
// __syncthreads. Aggregates die before the barrier (only ss0/ss1 cross it)
// and are recomputed from the held x registers afterwards.
__global__ __launch_bounds__(128)
void hc_main_kernel(const float4* __restrict__ x,
                    const float4* __restrict__ w,
                    float4* __restrict__ out) {
    const int n0  = blockIdx.x * 2;      // first token (pair never crosses batch)
    const int b   = n0 >> 12;            // / 4096
    const int t   = n0 & (T_LEN - 1);
    const int tid = threadIdx.x;         // 0..127

    const long strideS = (long)T_LEN * DV;
    const long pA = (long)(b * 4) * strideS + (long)t * DV + tid;  // token0 chunk A
    const long pB = pA + 128;                                      // token0 chunk B
    const long qA = pA + DV;                                       // token1 chunk A
    const long qB = qA + 128;                                      // token1 chunk B

    // 16 param-independent streaming loads, front-batched
    const float4 p0A = __ldcs(x + pA);
    const float4 p1A = __ldcs(x + pA + strideS);
    const float4 p2A = __ldcs(x + pA + 2 * strideS);
    const float4 p3A = __ldcs(x + pA + 3 * strideS);
    const float4 p0B = __ldcs(x + pB);
    const float4 p1B = __ldcs(x + pB + strideS);
    const float4 p2B = __ldcs(x + pB + 2 * strideS);
    const float4 p3B = __ldcs(x + pB + 3 * strideS);
    const float4 q0A = __ldcs(x + qA);
    const float4 q1A = __ldcs(x + qA + strideS);
    const float4 q2A = __ldcs(x + qA + 2 * strideS);
    const float4 q3A = __ldcs(x + qA + 3 * strideS);
    const float4 q0B = __ldcs(x + qB);
    const float4 q1B = __ldcs(x + qB + strideS);
    const float4 q2B = __ldcs(x + qB + 2 * strideS);
    const float4 q3B = __ldcs(x + qB + 3 * strideS);

    cudaGridDependencySynchronize();

    const float hp0 = g_hc_params[0], hp1 = g_hc_params[1];
    const float hp2 = g_hc_params[2], hp3 = g_hc_params[3];

    // sums of squares for both tokens; aggregates die here
    float ss0, ss1;
    {
        float ax, ay, az, aw;
        ax = hp0 * p0A.x + hp1 * p1A.x + hp2 * p2A.x + hp3 * p3A.x;
        ay = hp0 * p0A.y + hp1 * p1A.y + hp2 * p2A.y + hp3 * p3A.y;
        az = hp0 * p0A.z + hp1 * p1A.z + hp2 * p2A.z + hp3 * p3A.z;
        aw = hp0 * p0A.w + hp1 * p1A.w + hp2 * p2A.w + hp3 * p3A.w;
        ss0 = ax * ax + ay * ay + az * az + aw * aw;
        ax = hp0 * p0B.x + hp1 * p1B.x + hp2 * p2B.x + hp3 * p3B.x;
        ay = hp0 * p0B.y + hp1 * p1B.y + hp2 * p2B.y + hp3 * p3B.y;
        az = hp0 * p0B.z + hp1 * p1B.z + hp2 * p2B.z + hp3 * p3B.z;
        aw = hp0 * p0B.w + hp1 * p1B.w + hp2 * p2B.w + hp3 * p3B.w;
        ss0 += ax * ax + ay * ay + az * az + aw * aw;
        ax = hp0 * q0A.x + hp1 * q1A.x + hp2 * q2A.x + hp3 * q3A.x;
        ay = hp0 * q0A.y + hp1 * q1A.y + hp2 * q2A.y + hp3 * q3A.y;
        az = hp0 * q0A.z + hp1 * q1A.z + hp2 * q2A.z + hp3 * q3A.z;
        aw = hp0 * q0A.w + hp1 * q1A.w + hp2 * q2A.w + hp3 * q3A.w;
        ss1 = ax * ax + ay * ay + az * az + aw * aw;
        ax = hp0 * q0B.x + hp1 * q1B.x + hp2 * q2B.x + hp3 * q3B.x;
        ay = hp0 * q0B.y + hp1 * q1B.y + hp2 * q2B.y + hp3 * q3B.y;
        az = hp0 * q0B.z + hp1 * q1B.z + hp2 * q2B.z + hp3 * q3B.z;
        aw = hp0 * q0B.w + hp1 * q1B.w + hp2 * q2B.w + hp3 * q3B.w;
        ss1 += ax * ax + ay * ay + az * az + aw * aw;
    }

    __shared__ float wsum0[4], wsum1[4];
    #pragma unroll
    for (int off = 16; off > 0; off >>= 1) {
        ss0 += __shfl_xor_sync(0xFFFFFFFFu, ss0, off);
        ss1 += __shfl_xor_sync(0xFFFFFFFFu, ss1, off);
    }
    if ((tid & 31) == 0) {
        wsum0[tid >> 5] = ss0;
        wsum1[tid >> 5] = ss1;
    }
    __syncthreads();     // ONE barrier for both tokens

    const float tot0 = (wsum0[0] + wsum0[1]) + (wsum0[2] + wsum0[3]);
    const float tot1 = (wsum1[0] + wsum1[1]) + (wsum1[2] + wsum1[3]);
    const float ir0 = rsqrtf(tot0 * (1.0f / (float)D_DIM) + EPS);
    const float ir1 = rsqrtf(tot1 * (1.0f / (float)D_DIM) + EPS);

    // w loaded post-barrier: 4KB broadcast, L1/L2-hot
    const float4 wa = w[tid];
    const float4 wb = w[tid + 128];

    const float c0 = g_hc_params[4], c1 = g_hc_params[5];
    const float c2 = g_hc_params[6], c3 = g_hc_params[7];

    float4 xn, o;

    // ---- token0 chunk A ----
    xn.x = (hp0 * p0A.x + hp1 * p1A.x + hp2 * p2A.x + hp3 * p3A.x) * ir0 * wa.x;
    xn.y = (hp0 * p0A.y + hp1 * p1A.y + hp2 * p2A.y + hp3 * p3A.y) * ir0 * wa.y;
    xn.z = (hp0 * p0A.z + hp1 * p1A.z + hp2 * p2A.z + hp3 * p3A.z) * ir0 * wa.z;
    xn.w = (hp0 * p0A.w + hp1 * p1A.w + hp2 * p2A.w + hp3 * p3A.w) * ir0 * wa.w;
    o.x = p0A.x + c0 * xn.x; o.y = p0A.y + c0 * xn.y;
    o.z = p0A.z + c0 * xn.z; o.w = p0A.w + c0 * xn.w;
    __stcs(out + pA, o);
    o.x = p1A.x + c1 * xn.x; o.y = p1A.y + c1 * xn.y;
    o.z = p1A.z + c1 * xn.z; o.w = p1A.w + c1 * xn.w;
    __stcs(out + pA + strideS, o);
    o.x = p2A.x + c2 * xn.x; o.y = p2A.y + c2 * xn.y;
    o.z = p2A.z + c2 * xn.z; o.w = p2A.w + c2 * xn.w;
    __stcs(out + pA + 2 * strideS, o);
    o.x = p3A.x + c3 * xn.x; o.y = p3A.y + c3 * xn.y;
    o.z = p3A.z + c3 * xn.z; o.w = p3A.w + c3 * xn.w;
    __stcs(out + pA + 3 * strideS, o);

    // ---- token0 chunk B ----
    xn.x = (hp0 * p0B.x + hp1 * p1B.x + hp2 * p2B.x + hp3 * p3B.x) * ir0 * wb.x;
    xn.y = (hp0 * p0B.y + hp1 * p1B.y + hp2 * p2B.y + hp3 * p3B.y) * ir0 * wb.y;
    xn.z = (hp0 * p0B.z + hp1 * p1B.z + hp2 * p2B.z + hp3 * p3B.z) * ir0 * wb.z;
    xn.w = (hp0 * p0B.w + hp1 * p1B.w + hp2 * p2B.w + hp3 * p3B.w) * ir0 * wb.w;
    o.x = p0B.x + c0 * xn.x; o.y = p0B.y + c0 * xn.y;
    o.z = p0B.z + c0 * xn.z; o.w = p0B.w + c0 * xn.w;
    __stcs(out + pB, o);
    o.x = p1B.x + c1 * xn.x; o.y = p1B.y + c1 * xn.y;
    o.z = p1B.z + c1 * xn.z; o.w = p1B.w + c1 * xn.w;
    __stcs(out + pB + strideS, o);
    o.x = p2B.x + c2 * xn.x; o.y = p2B.y + c2 * xn.y;
    o.z = p2B.z + c2 * xn.z; o.w = p2B.w + c2 * xn.w;
    __stcs(out + pB + 2 * strideS, o);
    o.x = p3B.x + c3 * xn.x; o.y = p3B.y + c3 * xn.y;
    o.z = p3B.z + c3 * xn.z; o.w = p3B.w + c3 * xn.w;
    __stcs(out + pB + 3 * strideS, o);

    // ---- token1 chunk A ----
    xn.x = (hp0 * q0A.x + hp1 * q1A.x + hp2 * q2A.x + hp3 * q3A.x) * ir1 * wa.x;
    xn.y = (hp0 * q0A.y + hp1 * q1A.y + hp2 * q2A.y + hp3 * q3A.y) * ir1 * wa.y;
    xn.z = (hp0 * q0A.z + hp1 * q1A.z + hp2 * q2A.z + hp3 * q3A.z) * ir1 * wa.z;
    xn.w = (hp0 * q0A.w + hp1 * q1A.w + hp2 * q2A.w + hp3 * q3A.w) * ir1 * wa.w;
    o.x = q0A.x + c0 * xn.x; o.y = q0A.y + c0 * xn.y;
    o.z = q0A.z + c0 * xn.z; o.w = q0A.w + c0 * xn.w;
    __stcs(out + qA, o);
    o.x = q1A.x + c1 * xn.x; o.y = q1A.y + c1 * xn.y;
    o.z = q1A.z + c1 * xn.z; o.w = q1A.w + c1 * xn.w;
    __stcs(out + qA + strideS, o);
    o.x = q2A.x + c2 * xn.x; o.y = q2A.y + c2 * xn.y;
    o.z = q2A.z + c2 * xn.z; o.w = q2A.w + c2 * xn.w;
    __stcs(out + qA + 2 * strideS, o);
    o.x = q3A.x + c3 * xn.x; o.y = q3A.y + c3 * xn.y;
    o.z = q3A.z + c3 * xn.z; o.w = q3A.w + c3 * xn.w;
    __stcs(out + qA + 3 * strideS, o);

    // ---- token1 chunk B ----
    xn.x = (hp0 * q0B.x + hp1 * q1B.x + hp2 * q2B.x + hp3 * q3B.x) * ir1 * wb.x;
    xn.y = (hp0 * q0B.y + hp1 * q1B.y + hp2 * q2B.y + hp3 * q3B.y) * ir1 * wb.y;
    xn.z = (hp0 * q0B.z + hp1 * q1B.z + hp2 * q2B.z + hp3 * q3B.z) * ir1 * wb.z;
    xn.w = (hp0 * q0B.w + hp1 * q1B.w + hp2 * q2B.w + hp3 * q3B.w) * ir1 * wb.w;
    o.x = q0B.x + c0 * xn.x; o.y = q0B.y + c0 * xn.y;
    o.z = q0B.z + c0 * xn.z; o.w = q0B.w + c0 * xn.w;
    __stcs(out + qB, o);
    o.x = q1B.x + c1 * xn.x; o.y = q1B.y + c1 * xn.y;
    o.z = q1B.z + c1 * xn.z; o.w = q1B.w + c1 * xn.w;
    __stcs(out + qB + strideS, o);
    o.x = q2B.x + c2 * xn.x; o.y = q2B.y + c2 * xn.y;
    o.z = q2B.z + c2 * xn.z; o.w = q2B.w + c2 * xn.w;
    __stcs(out + qB + 2 * strideS, o);
    o.x = q3B.x + c3 * xn.x; o.y = q3B.y + c3 * xn.y;
    o.z = q3B.z + c3 * xn.z; o.w = q3B.w + c3 * xn.w;
    __stcs(out + qB + 3 * strideS, o);
}

extern "C" void kernel_launch(void* const* d_in, const int* in_sizes, int n_in,
                              void* d_out, int out_size) {
    const float* residuals      = (const float*)d_in[0];  // (B*S, T, D) fp32
    const float* rmsnorm_weight = (const float*)d_in[1];  // (D,)
    const float* H_pre_logits   = (const float*)d_in[2];  // (S,)
    const float* H_post_logits  = (const float*)d_in[3];  // (S,)
    const float* H_res          = (const float*)d_in[4];  // (S, S)
    float* out = (float*)d_out;

    const int BS = in_sizes[0] / (T_LEN * D_DIM);  // B*S = 16
    const int B  = BS / S_STREAMS;                 // 4
    const int n_tokens = B * T_LEN;                // 16384

    hc_precompute_kernel<<<1, 1>>>(H_pre_logits, H_post_logits, H_res);

    cudaLaunchConfig_t cfg = {};
    cfg.gridDim  = dim3(n_tokens / 2, 1, 1);       // 2 tokens per block
    cfg.blockDim = dim3(128, 1, 1);
    cfg.dynamicSmemBytes = 0;
    cfg.stream = 0;
    cudaLaunchAttribute attrs[1];
    attrs[0].id = cudaLaunchAttributeProgrammaticStreamSerialization;
    attrs[0].val.programmaticStreamSerializationAllowed = 1;
    cfg.attrs = attrs;
    cfg.numAttrs = 1;

    cudaLaunchKernelEx(&cfg, hc_main_kernel,
                       (const float4*)residuals,
                       (const float4*)rmsnorm_weight,
                       (float4*)out);
}

// round 14
// speedup vs baseline: 1.0046x; 1.0046x over previous
#include <cuda_runtime.h>
#include <math.h>

// S=4, B=4, T=4096, D=1024 (fixed per reference setup_inputs)
#define S_STREAMS 4
#define T_LEN 4096
#define D_DIM 1024
#define DV (D_DIM / 4)          // 256 float4 per row
#define SINKHORN_ITERS 20
#define EPS 1e-5f

// precomputed scalars: [0..3]=h_pre, [4..7]=c
__device__ float g_hc_params[8];

// Primary kernel (PDL): trigger the dependent launch IMMEDIATELY, then do the
// ~1.3k-cycle serial fast-math precompute.
__global__ void hc_precompute_kernel(const float* __restrict__ H_pre_logits,
                                     const float* __restrict__ H_post_logits,
                                     const float* __restrict__ H_res) {
    cudaTriggerProgrammaticLaunchCompletion();

    float M[4][4];
    #pragma unroll
    for (int i = 0; i < 4; i++)
        #pragma unroll
        for (int j = 0; j < 4; j++)
            M[i][j] = __expf(H_res[i * 4 + j]);

    #pragma unroll 4
    for (int it = 0; it < SINKHORN_ITERS; it++) {
        #pragma unroll
        for (int i = 0; i < 4; i++) {
            float s = (M[i][0] + M[i][1]) + (M[i][2] + M[i][3]) + EPS;
            float inv = __fdividef(1.0f, s);
            #pragma unroll
            for (int j = 0; j < 4; j++) M[i][j] *= inv;
        }
        #pragma unroll
        for (int j = 0; j < 4; j++) {
            float s = (M[0][j] + M[1][j]) + (M[2][j] + M[3][j]) + EPS;
            float inv = __fdividef(1.0f, s);
            #pragma unroll
            for (int i = 0; i < 4; i++) M[i][j] *= inv;
        }
    }

    float h_post[4];
    #pragma unroll
    for (int r = 0; r < 4; r++)
        h_post[r] = 2.0f * __fdividef(1.0f, 1.0f + __expf(-H_post_logits[r]));

    #pragma unroll
    for (int s = 0; s < 4; s++) {
        g_hc_params[s] = __fdividef(1.0f, 1.0f + __expf(-H_pre_logits[s]));
        float c = 0.0f;
        #pragma unroll
        for (int r = 0; r < 4; r++) c += M[s][r] * h_post[r];
        g_hc_params[4 + s] = c;
    }
}

// Secondary kernel (PDL): one 128-thread block per token; each thread owns
// float4 chunks tid and tid+128 -> 8 independent front-batched LDG.128
// (MLP_p1=8, 4KB/warp in flight). Single 4-warp barrier; w broadcast loaded
// post-barrier (L1-hot). Empirically optimal config (R11: 76.35us main,
// 79.9% DRAM, 6.33 TB/s).
__global__ __launch_bounds__(128, 8)
void hc_main_kernel(const float4* __restrict__ x,
                    const float4* __restrict__ w,
                    float4* __restrict__ out) {
    const int n   = blockIdx.x;          // 0 .. B*T-1
    const int b   = n >> 12;             // / 4096
    const int t   = n & (T_LEN - 1);
    const int tid = threadIdx.x;         // 0..127

    const long strideS = (long)T_LEN * DV;
    const long baseA   = (long)(b * 4) * strideS + (long)t * DV + tid;
    const long baseB   = baseA + 128;

    // param-independent streaming loads FIRST: 8 independent LDG.128
    // (overlaps the precompute kernel via PDL)
    const float4 xa0 = __ldcs(x + baseA);
    const float4 xa1 = __ldcs(x + baseA + strideS);
    const float4 xa2 = __ldcs(x + baseA + 2 * strideS);
    const float4 xa3 = __ldcs(x + baseA + 3 * strideS);
    const float4 xb0 = __ldcs(x + baseB);
    const float4 xb1 = __ldcs(x + baseB + strideS);
    const float4 xb2 = __ldcs(x + baseB + 2 * strideS);
    const float4 xb3 = __ldcs(x + baseB + 3 * strideS);

    cudaGridDependencySynchronize();

    const float hp0 = g_hc_params[0], hp1 = g_hc_params[1];
    const float hp2 = g_hc_params[2], hp3 = g_hc_params[3];
    const float c0  = g_hc_params[4], c1  = g_hc_params[5];
    const float c2  = g_hc_params[6], c3  = g_hc_params[7];

    float4 aA, aB;
    aA.x = hp0 * xa0.x + hp1 * xa1.x + hp2 * xa2.x + hp3 * xa3.x;
    aA.y = hp0 * xa0.y + hp1 * xa1.y + hp2 * xa2.y + hp3 * xa3.y;
    aA.z = hp0 * xa0.z + hp1 * xa1.z + hp2 * xa2.z + hp3 * xa3.z;
    aA.w = hp0 * xa0.w + hp1 * xa1.w + hp2 * xa2.w + hp3 * xa3.w;
    aB.x = hp0 * xb0.x + hp1 * xb1.x + hp2 * xb2.x + hp3 * xb3.x;
    aB.y = hp0 * xb0.y + hp1 * xb1.y + hp2 * xb2.y + hp3 * xb3.y;
    aB.z = hp0 * xb0.z + hp1 * xb1.z + hp2 * xb2.z + hp3 * xb3.z;
    aB.w = hp0 * xb0.w + hp1 * xb1.w + hp2 * xb2.w + hp3 * xb3.w;

    float ss = aA.x * aA.x + aA.y * aA.y + aA.z * aA.z + aA.w * aA.w
             + aB.x * aB.x + aB.y * aB.y + aB.z * aB.z + aB.w * aB.w;

    __shared__ float warp_sums[4];
    #pragma unroll
    for (int off = 16; off > 0; off >>= 1)
        ss += __shfl_xor_sync(0xFFFFFFFFu, ss, off);
    if ((tid & 31) == 0) warp_sums[tid >> 5] = ss;
    __syncthreads();     // single barrier, 4 warps

    const float tot = (warp_sums[0] + warp_sums[1]) + (warp_sums[2] + warp_sums[3]);
    const float inv_rms = rsqrtf(tot * (1.0f / (float)D_DIM) + EPS);

    // w loaded post-barrier: 4KB broadcast, L1/L2-hot across all blocks
    const float4 wa = w[tid];
    const float4 wb = w[tid + 128];

    float4 xnA, xnB;
    xnA.x = aA.x * inv_rms * wa.x;
    xnA.y = aA.y * inv_rms * wa.y;
    xnA.z = aA.z * inv_rms * wa.z;
    xnA.w = aA.w * inv_rms * wa.w;
    xnB.x = aB.x * inv_rms * wb.x;
    xnB.y = aB.y * inv_rms * wb.y;
    xnB.z = aB.z * inv_rms * wb.z;
    xnB.w = aB.w * inv_rms * wb.w;

    float4 o;
    o.x = xa0.x + c0 * xnA.x; o.y = xa0.y + c0 * xnA.y;
    o.z = xa0.z + c0 * xnA.z; o.w = xa0.w + c0 * xnA.w;
    __stcs(out + baseA, o);
    o.x = xb0.x + c0 * xnB.x; o.y = xb0.y + c0 * xnB.y;
    o.z = xb0.z + c0 * xnB.z; o.w = xb0.w + c0 * xnB.w;
    __stcs(out + baseB, o);

    o.x = xa1.x + c1 * xnA.x; o.y = xa1.y + c1 * xnA.y;
    o.z = xa1.z + c1 * xnA.z; o.w = xa1.w + c1 * xnA.w;
    __stcs(out + baseA + strideS, o);
    o.x = xb1.x + c1 * xnB.x; o.y = xb1.y + c1 * xnB.y;
    o.z = xb1.z + c1 * xnB.z; o.w = xb1.w + c1 * xnB.w;
    __stcs(out + baseB + strideS, o);

    o.x = xa2.x + c2 * xnA.x; o.y = xa2.y + c2 * xnA.y;
    o.z = xa2.z + c2 * xnA.z; o.w = xa2.w + c2 * xnA.w;
    __stcs(out + baseA + 2 * strideS, o);
    o.x = xb2.x + c2 * xnB.x; o.y = xb2.y + c2 * xnB.y;
    o.z = xb2.z + c2 * xnB.z; o.w = xb2.w + c2 * xnB.w;
    __stcs(out + baseB + 2 * strideS, o);

    o.x = xa3.x + c3 * xnA.x; o.y = xa3.y + c3 * xnA.y;
    o.z = xa3.z + c3 * xnA.z; o.w = xa3.w + c3 * xnA.w;
    __stcs(out + baseA + 3 * strideS, o);
    o.x = xb3.x + c3 * xnB.x; o.y = xb3.y + c3 * xnB.y;
    o.z = xb3.z + c3 * xnB.z; o.w = xb3.w + c3 * xnB.w;
    __stcs(out + baseB + 3 * strideS, o);
}

extern "C" void kernel_launch(void* const* d_in, const int* in_sizes, int n_in,
                              void* d_out, int out_size) {
    const float* residuals      = (const float*)d_in[0];  // (B*S, T, D) fp32
    const float* rmsnorm_weight = (const float*)d_in[1];  // (D,)
    const float* H_pre_logits   = (const float*)d_in[2];  // (S,)
    const float* H_post_logits  = (const float*)d_in[3];  // (S,)
    const float* H_res          = (const float*)d_in[4];  // (S, S)
    float* out = (float*)d_out;

    const int BS = in_sizes[0] / (T_LEN * D_DIM);  // B*S = 16
    const int B  = BS / S_STREAMS;                 // 4
    const int n_tokens = B * T_LEN;                // 16384

    hc_precompute_kernel<<<1, 1>>>(H_pre_logits, H_post_logits, H_res);

    cudaLaunchConfig_t cfg = {};
    cfg.gridDim  = dim3(n_tokens, 1, 1);
    cfg.blockDim = dim3(128, 1, 1);
    cfg.dynamicSmemBytes = 0;
    cfg.stream = 0;
    cudaLaunchAttribute attrs[1];
    attrs[0].id = cudaLaunchAttributeProgrammaticStreamSerialization;
    attrs[0].val.programmaticStreamSerializationAllowed = 1;
    cfg.attrs = attrs;
    cfg.numAttrs = 1;

    cudaLaunchKernelEx(&cfg, hc_main_kernel,
                       (const float4*)residuals,
                       (const float4*)rmsnorm_weight,
                       (float4*)out);
}

// round 15
// speedup vs baseline: 1.0053x; 1.0008x over previous
#include <cuda_runtime.h>
#include <math.h>

// S=4, B=4, T=4096, D=1024 (fixed per reference setup_inputs)
#define S_STREAMS 4
#define T_LEN 4096
#define D_DIM 1024
#define DV (D_DIM / 4)          // 256 float4 per row
#define SINKHORN_ITERS 20
#define EPS 1e-5f

// precomputed scalars as two float4: [0]=h_pre(0..3), [1]=c(0..3)
__device__ float4 g_hc_params[2];

// Primary kernel (PDL): trigger the dependent launch IMMEDIATELY, then do the
// ~1.3k-cycle serial fast-math precompute.
__global__ void hc_precompute_kernel(const float* __restrict__ H_pre_logits,
                                     const float* __restrict__ H_post_logits,
                                     const float* __restrict__ H_res) {
    cudaTriggerProgrammaticLaunchCompletion();

    float M[4][4];
    #pragma unroll
    for (int i = 0; i < 4; i++)
        #pragma unroll
        for (int j = 0; j < 4; j++)
            M[i][j] = __expf(H_res[i * 4 + j]);

    #pragma unroll 4
    for (int it = 0; it < SINKHORN_ITERS; it++) {
        #pragma unroll
        for (int i = 0; i < 4; i++) {
            float s = (M[i][0] + M[i][1]) + (M[i][2] + M[i][3]) + EPS;
            float inv = __fdividef(1.0f, s);
            #pragma unroll
            for (int j = 0; j < 4; j++) M[i][j] *= inv;
        }
        #pragma unroll
        for (int j = 0; j < 4; j++) {
            float s = (M[0][j] + M[1][j]) + (M[2][j] + M[3][j]) + EPS;
            float inv = __fdividef(1.0f, s);
            #pragma unroll
            for (int i = 0; i < 4; i++) M[i][j] *= inv;
        }
    }

    float h_post[4];
    #pragma unroll
    for (int r = 0; r < 4; r++)
        h_post[r] = 2.0f * __fdividef(1.0f, 1.0f + __expf(-H_post_logits[r]));

    float4 hp, cc;
    hp.x = __fdividef(1.0f, 1.0f + __expf(-H_pre_logits[0]));
    hp.y = __fdividef(1.0f, 1.0f + __expf(-H_pre_logits[1]));
    hp.z = __fdividef(1.0f, 1.0f + __expf(-H_pre_logits[2]));
    hp.w = __fdividef(1.0f, 1.0f + __expf(-H_pre_logits[3]));
    cc.x = M[0][0] * h_post[0] + M[0][1] * h_post[1] + M[0][2] * h_post[2] + M[0][3] * h_post[3];
    cc.y = M[1][0] * h_post[0] + M[1][1] * h_post[1] + M[1][2] * h_post[2] + M[1][3] * h_post[3];
    cc.z = M[2][0] * h_post[0] + M[2][1] * h_post[1] + M[2][2] * h_post[2] + M[2][3] * h_post[3];
    cc.w = M[3][0] * h_post[0] + M[3][1] * h_post[1] + M[3][2] * h_post[2] + M[3][3] * h_post[3];
    g_hc_params[0] = hp;
    g_hc_params[1] = cc;
}

// Secondary kernel (PDL): one 128-thread block per token; each thread owns
// float4 chunks tid and tid+128 -> 8 independent front-batched LDG.128 plus
// the two w broadcasts, all issued BEFORE the grid-dependency wait (overlap
// with the precompute via PDL). Single 4-warp barrier. Best-measured-total
// configuration (R9: 82.5us).
__global__ __launch_bounds__(128, 8)
void hc_main_kernel(const float4* __restrict__ x,
                    const float4* __restrict__ w,
                    float4* __restrict__ out) {
    const int n   = blockIdx.x;          // 0 .. B*T-1
    const int b   = n >> 12;             // / 4096
    const int t   = n & (T_LEN - 1);
    const int tid = threadIdx.x;         // 0..127

    const long strideS = (long)T_LEN * DV;
    const long baseA   = (long)(b * 4) * strideS + (long)t * DV + tid;
    const long baseB   = baseA + 128;

    // param-independent loads FIRST: 8 streaming LDG.128 + 2 w broadcasts
    const float4 xa0 = __ldcs(x + baseA);
    const float4 xa1 = __ldcs(x + baseA + strideS);
    const float4 xa2 = __ldcs(x + baseA + 2 * strideS);
    const float4 xa3 = __ldcs(x + baseA + 3 * strideS);
    const float4 xb0 = __ldcs(x + baseB);
    const float4 xb1 = __ldcs(x + baseB + strideS);
    const float4 xb2 = __ldcs(x + baseB + 2 * strideS);
    const float4 xb3 = __ldcs(x + baseB + 3 * strideS);
    const float4 wa  = w[tid];
    const float4 wb  = w[tid + 128];

    cudaGridDependencySynchronize();

    // two vector loads instead of 8 scalar LDGs
    const float4 hp = g_hc_params[0];
    const float4 cv = g_hc_params[1];
    const float hp0 = hp.x, hp1 = hp.y, hp2 = hp.z, hp3 = hp.w;
    const float c0  = cv.x, c1  = cv.y, c2  = cv.z, c3  = cv.w;

    float4 aA, aB;
    aA.x = hp0 * xa0.x + hp1 * xa1.x + hp2 * xa2.x + hp3 * xa3.x;
    aA.y = hp0 * xa0.y + hp1 * xa1.y + hp2 * xa2.y + hp3 * xa3.y;
    aA.z = hp0 * xa0.z + hp1 * xa1.z + hp2 * xa2.z + hp3 * xa3.z;
    aA.w = hp0 * xa0.w + hp1 * xa1.w + hp2 * xa2.w + hp3 * xa3.w;
    aB.x = hp0 * xb0.x + hp1 * xb1.x + hp2 * xb2.x + hp3 * xb3.x;
    aB.y = hp0 * xb0.y + hp1 * xb1.y + hp2 * xb2.y + hp3 * xb3.y;
    aB.z = hp0 * xb0.z + hp1 * xb1.z + hp2 * xb2.z + hp3 * xb3.z;
    aB.w = hp0 * xb0.w + hp1 * xb1.w + hp2 * xb2.w + hp3 * xb3.w;

    float ss = aA.x * aA.x + aA.y * aA.y + aA.z * aA.z + aA.w * aA.w
             + aB.x * aB.x + aB.y * aB.y + aB.z * aB.z + aB.w * aB.w;

    __shared__ float warp_sums[4];
    #pragma unroll
    for (int off = 16; off > 0; off >>= 1)
        ss += __shfl_xor_sync(0xFFFFFFFFu, ss, off);
    if ((tid & 31) == 0) warp_sums[tid >> 5] = ss;
    __syncthreads();     // single barrier, 4 warps

    const float tot = (warp_sums[0] + warp_sums[1]) + (warp_sums[2] + warp_sums[3]);
    const float inv_rms = rsqrtf(tot * (1.0f / (float)D_DIM) + EPS);

    float4 xnA, xnB;
    xnA.x = aA.x * inv_rms * wa.x;
    xnA.y = aA.y * inv_rms * wa.y;
    xnA.z = aA.z * inv_rms * wa.z;
    xnA.w = aA.w * inv_rms * wa.w;
    xnB.x = aB.x * inv_rms * wb.x;
    xnB.y = aB.y * inv_rms * wb.y;
    xnB.z = aB.z * inv_rms * wb.z;
    xnB.w = aB.w * inv_rms * wb.w;

    float4 o;
    o.x = xa0.x + c0 * xnA.x; o.y = xa0.y + c0 * xnA.y;
    o.z = xa0.z + c0 * xnA.z; o.w = xa0.w + c0 * xnA.w;
    __stcs(out + baseA, o);
    o.x = xb0.x + c0 * xnB.x; o.y = xb0.y + c0 * xnB.y;
    o.z = xb0.z + c0 * xnB.z; o.w = xb0.w + c0 * xnB.w;
    __stcs(out + baseB, o);

    o.x = xa1.x + c1 * xnA.x; o.y = xa1.y + c1 * xnA.y;
    o.z = xa1.z + c1 * xnA.z; o.w = xa1.w + c1 * xnA.w;
    __stcs(out + baseA + strideS, o);
    o.x = xb1.x + c1 * xnB.x; o.y = xb1.y + c1 * xnB.y;
    o.z = xb1.z + c1 * xnB.z; o.w = xb1.w + c1 * xnB.w;
    __stcs(out + baseB + strideS, o);

    o.x = xa2.x + c2 * xnA.x; o.y = xa2.y + c2 * xnA.y;
    o.z = xa2.z + c2 * xnA.z; o.w = xa2.w + c2 * xnA.w;
    __stcs(out + baseA + 2 * strideS, o);
    o.x = xb2.x + c2 * xnB.x; o.y = xb2.y + c2 * xnB.y;
    o.z = xb2.z + c2 * xnB.z; o.w = xb2.w + c2 * xnB.w;
    __stcs(out + baseB + 2 * strideS, o);

    o.x = xa3.x + c3 * xnA.x; o.y = xa3.y + c3 * xnA.y;
    o.z = xa3.z + c3 * xnA.z; o.w = xa3.w + c3 * xnA.w;
    __stcs(out + baseA + 3 * strideS, o);
    o.x = xb3.x + c3 * xnB.x; o.y = xb3.y + c3 * xnB.y;
    o.z = xb3.z + c3 * xnB.z; o.w = xb3.w + c3 * xnB.w;
    __stcs(out + baseB + 3 * strideS, o);
}

extern "C" void kernel_launch(void* const* d_in, const int* in_sizes, int n_in,
                              void* d_out, int out_size) {
    const float* residuals      = (const float*)d_in[0];  // (B*S, T, D) fp32
    const float* rmsnorm_weight = (const float*)d_in[1];  // (D,)
    const float* H_pre_logits   = (const float*)d_in[2];  // (S,)
    const float* H_post_logits  = (const float*)d_in[3];  // (S,)
    const float* H_res          = (const float*)d_in[4];  // (S, S)
    float* out = (float*)d_out;

    const int BS = in_sizes[0] / (T_LEN * D_DIM);  // B*S = 16
    const int B  = BS / S_STREAMS;                 // 4
    const int n_tokens = B * T_LEN;                // 16384

    hc_precompute_kernel<<<1, 1>>>(H_pre_logits, H_post_logits, H_res);

    cudaLaunchConfig_t cfg = {};
    cfg.gridDim  = dim3(n_tokens, 1, 1);
    cfg.blockDim = dim3(128, 1, 1);
    cfg.dynamicSmemBytes = 0;
    cfg.stream = 0;
    cudaLaunchAttribute attrs[1];
    attrs[0].id = cudaLaunchAttributeProgrammaticStreamSerialization;
    attrs[0].val.programmaticStreamSerializationAllowed = 1;
    cfg.attrs = attrs;
    cfg.numAttrs = 1;

    cudaLaunchKernelEx(&cfg, hc_main_kernel,
                       (const float4*)residuals,
                       (const float4*)rmsnorm_weight,
                       (float4*)out);
}

// round 16
// speedup vs baseline: 1.0061x; 1.0008x over previous
#include <cuda_runtime.h>
#include <math.h>

// S=4, B=4, T=4096, D=1024 (fixed per reference setup_inputs)
#define S_STREAMS 4
#define T_LEN 4096
#define D_DIM 1024
#define DV (D_DIM / 4)          // 256 float4 per row
#define SINKHORN_ITERS 20
#define EPS 1e-5f

// precomputed scalars: [0..3]=h_pre, [4..7]=c
__device__ float g_hc_params[8];

// Primary kernel (PDL): trigger the dependent launch IMMEDIATELY, then do the
// ~1.3k-cycle serial fast-math precompute.
__global__ void hc_precompute_kernel(const float* __restrict__ H_pre_logits,
                                     const float* __restrict__ H_post_logits,
                                     const float* __restrict__ H_res) {
    cudaTriggerProgrammaticLaunchCompletion();

    float M[4][4];
    #pragma unroll
    for (int i = 0; i < 4; i++)
        #pragma unroll
        for (int j = 0; j < 4; j++)
            M[i][j] = __expf(H_res[i * 4 + j]);

    #pragma unroll 4
    for (int it = 0; it < SINKHORN_ITERS; it++) {
        #pragma unroll
        for (int i = 0; i < 4; i++) {
            float s = (M[i][0] + M[i][1]) + (M[i][2] + M[i][3]) + EPS;
            float inv = __fdividef(1.0f, s);
            #pragma unroll
            for (int j = 0; j < 4; j++) M[i][j] *= inv;
        }
        #pragma unroll
        for (int j = 0; j < 4; j++) {
            float s = (M[0][j] + M[1][j]) + (M[2][j] + M[3][j]) + EPS;
            float inv = __fdividef(1.0f, s);
            #pragma unroll
            for (int i = 0; i < 4; i++) M[i][j] *= inv;
        }
    }

    float h_post[4];
    #pragma unroll
    for (int r = 0; r < 4; r++)
        h_post[r] = 2.0f * __fdividef(1.0f, 1.0f + __expf(-H_post_logits[r]));

    #pragma unroll
    for (int s = 0; s < 4; s++) {
        g_hc_params[s] = __fdividef(1.0f, 1.0f + __expf(-H_pre_logits[s]));
        float c = 0.0f;
        #pragma unroll
        for (int r = 0; r < 4; r++) c += M[s][r] * h_post[r];
        g_hc_params[4 + s] = c;
    }
}

// Secondary kernel (PDL): one 128-thread block per token; each thread owns
// float4 chunks tid and tid+128 -> 8 independent front-batched LDG.128
// (MLP_p1=8, 4KB/warp in flight) plus the 2 w broadcasts, all issued BEFORE
// the grid-dependency wait. Single 4-warp barrier. Best-measured-total
// configuration (R9: 82.5us).
__global__ __launch_bounds__(128, 8)
void hc_main_kernel(const float4* __restrict__ x,
                    const float4* __restrict__ w,
                    float4* __restrict__ out) {
    const int n   = blockIdx.x;          // 0 .. B*T-1
    const int b   = n >> 12;             // / 4096
    const int t   = n & (T_LEN - 1);
    const int tid = threadIdx.x;         // 0..127

    const long strideS = (long)T_LEN * DV;
    const long baseA   = (long)(b * 4) * strideS + (long)t * DV + tid;
    const long baseB   = baseA + 128;

    // param-independent streaming loads FIRST: 8 independent LDG.128
    // (overlaps the precompute kernel via PDL)
    const float4 xa0 = __ldcs(x + baseA);
    const float4 xa1 = __ldcs(x + baseA + strideS);
    const float4 xa2 = __ldcs(x + baseA + 2 * strideS);
    const float4 xa3 = __ldcs(x + baseA + 3 * strideS);
    const float4 xb0 = __ldcs(x + baseB);
    const float4 xb1 = __ldcs(x + baseB + strideS);
    const float4 xb2 = __ldcs(x + baseB + 2 * strideS);
    const float4 xb3 = __ldcs(x + baseB + 3 * strideS);
    const float4 wa  = w[tid];
    const float4 wb  = w[tid + 128];

    cudaGridDependencySynchronize();

    const float hp0 = g_hc_params[0], hp1 = g_hc_params[1];
    const float hp2 = g_hc_params[2], hp3 = g_hc_params[3];
    const float c0  = g_hc_params[4], c1  = g_hc_params[5];
    const float c2  = g_hc_params[6], c3  = g_hc_params[7];

    float4 aA, aB;
    aA.x = hp0 * xa0.x + hp1 * xa1.x + hp2 * xa2.x + hp3 * xa3.x;
    aA.y = hp0 * xa0.y + hp1 * xa1.y + hp2 * xa2.y + hp3 * xa3.y;
    aA.z = hp0 * xa0.z + hp1 * xa1.z + hp2 * xa2.z + hp3 * xa3.z;
    aA.w = hp0 * xa0.w + hp1 * xa1.w + hp2 * xa2.w + hp3 * xa3.w;
    aB.x = hp0 * xb0.x + hp1 * xb1.x + hp2 * xb2.x + hp3 * xb3.x;
    aB.y = hp0 * xb0.y + hp1 * xb1.y + hp2 * xb2.y + hp3 * xb3.y;
    aB.z = hp0 * xb0.z + hp1 * xb1.z + hp2 * xb2.z + hp3 * xb3.z;
    aB.w = hp0 * xb0.w + hp1 * xb1.w + hp2 * xb2.w + hp3 * xb3.w;

    float ss = aA.x * aA.x + aA.y * aA.y + aA.z * aA.z + aA.w * aA.w
             + aB.x * aB.x + aB.y * aB.y + aB.z * aB.z + aB.w * aB.w;

    __shared__ float warp_sums[4];
    #pragma unroll
    for (int off = 16; off > 0; off >>= 1)
        ss += __shfl_xor_sync(0xFFFFFFFFu, ss, off);
    if ((tid & 31) == 0) warp_sums[tid >> 5] = ss;
    __syncthreads();     // single barrier, 4 warps

    const float tot = (warp_sums[0] + warp_sums[1]) + (warp_sums[2] + warp_sums[3]);
    const float inv_rms = rsqrtf(tot * (1.0f / (float)D_DIM) + EPS);

    float4 xnA, xnB;
    xnA.x = aA.x * inv_rms * wa.x;
    xnA.y = aA.y * inv_rms * wa.y;
    xnA.z = aA.z * inv_rms * wa.z;
    xnA.w = aA.w * inv_rms * wa.w;
    xnB.x = aB.x * inv_rms * wb.x;
    xnB.y = aB.y * inv_rms * wb.y;
    xnB.z = aB.z * inv_rms * wb.z;
    xnB.w = aB.w * inv_rms * wb.w;

    float4 o;
    o.x = xa0.x + c0 * xnA.x; o.y = xa0.y + c0 * xnA.y;
    o.z = xa0.z + c0 * xnA.z; o.w = xa0.w + c0 * xnA.w;
    __stcs(out + baseA, o);
    o.x = xb0.x + c0 * xnB.x; o.y = xb0.y + c0 * xnB.y;
    o.z = xb0.z + c0 * xnB.z; o.w = xb0.w + c0 * xnB.w;
    __stcs(out + baseB, o);

    o.x = xa1.x + c1 * xnA.x; o.y = xa1.y + c1 * xnA.y;
    o.z = xa1.z + c1 * xnA.z; o.w = xa1.w + c1 * xnA.w;
    __stcs(out + baseA + strideS, o);
    o.x = xb1.x + c1 * xnB.x; o.y = xb1.y + c1 * xnB.y;
    o.z = xb1.z + c1 * xnB.z; o.w = xb1.w + c1 * xnB.w;
    __stcs(out + baseB + strideS, o);

    o.x = xa2.x + c2 * xnA.x; o.y = xa2.y + c2 * xnA.y;
    o.z = xa2.z + c2 * xnA.z; o.w = xa2.w + c2 * xnA.w;
    __stcs(out + baseA + 2 * strideS, o);
    o.x = xb2.x + c2 * xnB.x; o.y = xb2.y + c2 * xnB.y;
    o.z = xb2.z + c2 * xnB.z; o.w = xb2.w + c2 * xnB.w;
    __stcs(out + baseB + 2 * strideS, o);

    o.x = xa3.x + c3 * xnA.x; o.y = xa3.y + c3 * xnA.y;
    o.z = xa3.z + c3 * xnA.z; o.w = xa3.w + c3 * xnA.w;
    __stcs(out + baseA + 3 * strideS, o);
    o.x = xb3.x + c3 * xnB.x; o.y = xb3.y + c3 * xnB.y;
    o.z = xb3.z + c3 * xnB.z; o.w = xb3.w + c3 * xnB.w;
    __stcs(out + baseB + 3 * strideS, o);
}

extern "C" void kernel_launch(void* const* d_in, const int* in_sizes, int n_in,
                              void* d_out, int out_size) {
    const float* residuals      = (const float*)d_in[0];  // (B*S, T, D) fp32
    const float* rmsnorm_weight = (const float*)d_in[1];  // (D,)
    const float* H_pre_logits   = (const float*)d_in[2];  // (S,)
    const float* H_post_logits  = (const float*)d_in[3];  // (S,)
    const float* H_res          = (const float*)d_in[4];  // (S, S)
    float* out = (float*)d_out;

    const int BS = in_sizes[0] / (T_LEN * D_DIM);  // B*S = 16
    const int B  = BS / S_STREAMS;                 // 4
    const int n_tokens = B * T_LEN;                // 16384

    hc_precompute_kernel<<<1, 1>>>(H_pre_logits, H_post_logits, H_res);

    cudaLaunchConfig_t cfg = {};
    cfg.gridDim  = dim3(n_tokens, 1, 1);
    cfg.blockDim = dim3(128, 1, 1);
    cfg.dynamicSmemBytes = 0;
    cfg.stream = 0;
    cudaLaunchAttribute attrs[1];
    attrs[0].id = cudaLaunchAttributeProgrammaticStreamSerialization;
    attrs[0].val.programmaticStreamSerializationAllowed = 1;
    cfg.attrs = attrs;
    cfg.numAttrs = 1;

    cudaLaunchKernelEx(&cfg, hc_main_kernel,
                       (const float4*)residuals,
                       (const float4*)rmsnorm_weight,
                       (float4*)out);
}

// round 17
// speedup vs baseline: 1.0173x; 1.0112x over previous
#include <cuda_runtime.h>
#include <math.h>

// S=4, B=4, T=4096, D=1024 (fixed per reference setup_inputs)
#define S_STREAMS 4
#define T_LEN 4096
#define D_DIM 1024
#define DV (D_DIM / 4)          // 256 float4 per row
#define SINKHORN_ITERS 20
#define EPS 1e-5f

// precomputed scalars: [0..3]=h_pre, [4..7]=c
__device__ float g_hc_params[8];

// Primary kernel (PDL): trigger the dependent launch IMMEDIATELY, then do the
// ~1.3k-cycle serial fast-math precompute. The secondary's
// cudaGridDependencySynchronize() guarantees visibility of these writes.
__global__ void hc_precompute_kernel(const float* __restrict__ H_pre_logits,
                                     const float* __restrict__ H_post_logits,
                                     const float* __restrict__ H_res) {
    cudaTriggerProgrammaticLaunchCompletion();

    float M[4][4];
    #pragma unroll
    for (int i = 0; i < 4; i++)
        #pragma unroll
        for (int j = 0; j < 4; j++)
            M[i][j] = __expf(H_res[i * 4 + j]);

    #pragma unroll 4
    for (int it = 0; it < SINKHORN_ITERS; it++) {
        #pragma unroll
        for (int i = 0; i < 4; i++) {
            float s = (M[i][0] + M[i][1]) + (M[i][2] + M[i][3]) + EPS;
            float inv = __fdividef(1.0f, s);
            #pragma unroll
            for (int j = 0; j < 4; j++) M[i][j] *= inv;
        }
        #pragma unroll
        for (int j = 0; j < 4; j++) {
            float s = (M[0][j] + M[1][j]) + (M[2][j] + M[3][j]) + EPS;
            float inv = __fdividef(1.0f, s);
            #pragma unroll
            for (int i = 0; i < 4; i++) M[i][j] *= inv;
        }
    }

    float h_post[4];
    #pragma unroll
    for (int r = 0; r < 4; r++)
        h_post[r] = 2.0f * __fdividef(1.0f, 1.0f + __expf(-H_post_logits[r]));

    #pragma unroll
    for (int s = 0; s < 4; s++) {
        g_hc_params[s] = __fdividef(1.0f, 1.0f + __expf(-H_pre_logits[s]));
        float c = 0.0f;
        #pragma unroll
        for (int r = 0; r < 4; r++) c += M[s][r] * h_post[r];
        g_hc_params[4 + s] = c;
    }
}

// Secondary kernel (PDL): one 128-thread block per token; each thread owns
// float4 chunks tid and tid+128 -> 8 independent front-batched LDG.128
// (MLP_p1=8, 4KB/warp in flight) plus the 2 w broadcasts, all issued BEFORE
// the grid-dependency wait (overlap with precompute via PDL). Single 4-warp
// barrier; evict-first on the once-touched x/out streams. Empirically
// converged optimum: total in [82.5, 84.4]us across 5 identical-config runs,
// main kernel 74.7-77.1us @ 79-81.5% DRAM (6.3-6.5 TB/s, mixed-stream HBM3e
// ceiling; minimal 512MB traffic).
__global__ __launch_bounds__(128, 8)
void hc_main_kernel(const float4* __restrict__ x,
                    const float4* __restrict__ w,
                    float4* __restrict__ out) {
    const int n   = blockIdx.x;          // 0 .. B*T-1
    const int b   = n >> 12;             // / 4096
    const int t   = n & (T_LEN - 1);
    const int tid = threadIdx.x;         // 0..127

    const long strideS = (long)T_LEN * DV;
    const long baseA   = (long)(b * 4) * strideS + (long)t * DV + tid;
    const long baseB   = baseA + 128;

    // param-independent streaming loads FIRST: 8 independent LDG.128
    const float4 xa0 = __ldcs(x + baseA);
    const float4 xa1 = __ldcs(x + baseA + strideS);
    const float4 xa2 = __ldcs(x + baseA + 2 * strideS);
    const float4 xa3 = __ldcs(x + baseA + 3 * strideS);
    const float4 xb0 = __ldcs(x + baseB);
    const float4 xb1 = __ldcs(x + baseB + strideS);
    const float4 xb2 = __ldcs(x + baseB + 2 * strideS);
    const float4 xb3 = __ldcs(x + baseB + 3 * strideS);
    const float4 wa  = w[tid];
    const float4 wb  = w[tid + 128];

    cudaGridDependencySynchronize();

    const float hp0 = g_hc_params[0], hp1 = g_hc_params[1];
    const float hp2 = g_hc_params[2], hp3 = g_hc_params[3];
    const float c0  = g_hc_params[4], c1  = g_hc_params[5];
    const float c2  = g_hc_params[6], c3  = g_hc_params[7];

    float4 aA, aB;
    aA.x = hp0 * xa0.x + hp1 * xa1.x + hp2 * xa2.x + hp3 * xa3.x;
    aA.y = hp0 * xa0.y + hp1 * xa1.y + hp2 * xa2.y + hp3 * xa3.y;
    aA.z = hp0 * xa0.z + hp1 * xa1.z + hp2 * xa2.z + hp3 * xa3.z;
    aA.w = hp0 * xa0.w + hp1 * xa1.w + hp2 * xa2.w + hp3 * xa3.w;
    aB.x = hp0 * xb0.x + hp1 * xb1.x + hp2 * xb2.x + hp3 * xb3.x;
    aB.y = hp0 * xb0.y + hp1 * xb1.y + hp2 * xb2.y + hp3 * xb3.y;
    aB.z = hp0 * xb0.z + hp1 * xb1.z + hp2 * xb2.z + hp3 * xb3.z;
    aB.w = hp0 * xb0.w + hp1 * xb1.w + hp2 * xb2.w + hp3 * xb3.w;

    float ss = aA.x * aA.x + aA.y * aA.y + aA.z * aA.z + aA.w * aA.w
             + aB.x * aB.x + aB.y * aB.y + aB.z * aB.z + aB.w * aB.w;

    __shared__ float warp_sums[4];
    #pragma unroll
    for (int off = 16; off > 0; off >>= 1)
        ss += __shfl_xor_sync(0xFFFFFFFFu, ss, off);
    if ((tid & 31) == 0) warp_sums[tid >> 5] = ss;
    __syncthreads();     // single barrier, 4 warps

    const float tot = (warp_sums[0] + warp_sums[1]) + (warp_sums[2] + warp_sums[3]);
    const float inv_rms = rsqrtf(tot * (1.0f / (float)D_DIM) + EPS);

    float4 xnA, xnB;
    xnA.x = aA.x * inv_rms * wa.x;
    xnA.y = aA.y * inv_rms * wa.y;
    xnA.z = aA.z * inv_rms * wa.z;
    xnA.w = aA.w * inv_rms * wa.w;
    xnB.x = aB.x * inv_rms * wb.x;
    xnB.y = aB.y * inv_rms * wb.y;
    xnB.z = aB.z * inv_rms * wb.z;
    xnB.w = aB.w * inv_rms * wb.w;

    float4 o;
    o.x = xa0.x + c0 * xnA.x; o.y = xa0.y + c0 * xnA.y;
    o.z = xa0.z + c0 * xnA.z; o.w = xa0.w + c0 * xnA.w;
    __stcs(out + baseA, o);
    o.x = xb0.x + c0 * xnB.x; o.y = xb0.y + c0 * xnB.y;
    o.z = xb0.z + c0 * xnB.z; o.w = xb0.w + c0 * xnB.w;
    __stcs(out + baseB, o);

    o.x = xa1.x + c1 * xnA.x; o.y = xa1.y + c1 * xnA.y;
    o.z = xa1.z + c1 * xnA.z; o.w = xa1.w + c1 * xnA.w;
    __stcs(out + baseA + strideS, o);
    o.x = xb1.x + c1 * xnB.x; o.y = xb1.y + c1 * xnB.y;
    o.z = xb1.z + c1 * xnB.z; o.w = xb1.w + c1 * xnB.w;
    __stcs(out + baseB + strideS, o);

    o.x = xa2.x + c2 * xnA.x; o.y = xa2.y + c2 * xnA.y;
    o.z = xa2.z + c2 * xnA.z; o.w = xa2.w + c2 * xnA.w;
    __stcs(out + baseA + 2 * strideS, o);
    o.x = xb2.x + c2 * xnB.x; o.y = xb2.y + c2 * xnB.y;
    o.z = xb2.z + c2 * xnB.z; o.w = xb2.w + c2 * xnB.w;
    __stcs(out + baseB + 2 * strideS, o);

    o.x = xa3.x + c3 * xnA.x; o.y = xa3.y + c3 * xnA.y;
    o.z = xa3.z + c3 * xnA.z; o.w = xa3.w + c3 * xnA.w;
    __stcs(out + baseA + 3 * strideS, o);
    o.x = xb3.x + c3 * xnB.x; o.y = xb3.y + c3 * xnB.y;
    o.z = xb3.z + c3 * xnB.z; o.w = xb3.w + c3 * xnB.w;
    __stcs(out + baseB + 3 * strideS, o);
}

extern "C" void kernel_launch(void* const* d_in, const int* in_sizes, int n_in,
                              void* d_out, int out_size) {
    const float* residuals      = (const float*)d_in[0];  // (B*S, T, D) fp32
    const float* rmsnorm_weight = (const float*)d_in[1];  // (D,)
    const float* H_pre_logits   = (const float*)d_in[2];  // (S,)
    const float* H_post_logits  = (const float*)d_in[3];  // (S,)
    const float* H_res          = (const float*)d_in[4];  // (S, S)
    float* out = (float*)d_out;

    const int BS = in_sizes[0] / (T_LEN * D_DIM);  // B*S = 16
    const int B  = BS / S_STREAMS;                 // 4
    const int n_tokens = B * T_LEN;                // 16384

    hc_precompute_kernel<<<1, 1>>>(H_pre_logits, H_post_logits, H_res);

    cudaLaunchConfig_t cfg = {};
    cfg.gridDim  = dim3(n_tokens, 1, 1);
    cfg.blockDim = dim3(128, 1, 1);
    cfg.dynamicSmemBytes = 0;
    cfg.stream = 0;
    cudaLaunchAttribute attrs[1];
    attrs[0].id = cudaLaunchAttributeProgrammaticStreamSerialization;
    attrs[0].val.programmaticStreamSerializationAllowed = 1;
    cfg.attrs = attrs;
    cfg.numAttrs = 1;

    cudaLaunchKernelEx(&cfg, hc_main_kernel,
                       (const float4*)residuals,
                       (const float4*)rmsnorm_weight,
                       (float4*)out);
}